// round 9
// baseline (speedup 1.0000x reference)
#include <cuda_runtime.h>

#define BATCH 4096
#define NCLS  10000
#define DIM   256
#define ALPHA 0.5f
#define CAP   64   // per-class row-list capacity (overflow handled exactly)

// Scratch (allocation-free: __device__ globals).
// Counters start zeroed (static init) and are RESTORED to zero by
// scale_gather_kernel -> no zero kernel. Dual counters (A/B) let the two
// warps covering one class row each own a private read-then-clean sequence
// (in-warp program order), eliminating all barriers in K2.
__device__ int g_cntA[NCLS];        // per-class count, read by warp of cols 0-31
__device__ int g_cntB[NCLS];        // per-class count, read by warp of cols 32-63
__device__ int g_label[BATCH];      // decoded label per row (overflow fallback)
__device__ int g_rows[NCLS * CAP];  // per-class row index list (8B aligned rows)

// ---------------------------------------------------------------------------
// K1: one block per batch row.
//  a) early-exit scan of the onehot row, 8 KB chunks (2 float4/thread, MLP=2)
//  b) finder thread: record label, append row to class list, bump BOTH counts
//  c) all threads: loss ||feat - centers[label]||^2 (gathers hide under the
//     BW-bound scan traffic of other resident blocks)
// ---------------------------------------------------------------------------
__global__ __launch_bounds__(256, 8)
void scan_loss_kernel(const float* __restrict__ onehot,
                      const float* __restrict__ feat,
                      const float* __restrict__ centers,
                      float* __restrict__ loss_out) {
    const int b = blockIdx.x;
    const int t = threadIdx.x;

    __shared__ int s_label;
    __shared__ float s_red[8];
    if (t == 0) s_label = -1;
    __syncthreads();

    const float4* row = reinterpret_cast<const float4*>(onehot + (size_t)b * NCLS);
    const int NV4 = NCLS / 4;  // 2500 float4s

    #pragma unroll 1
    for (int it = 0; it < (NV4 + 511) / 512; ++it) {
        const int i0 = it * 512 + t;
        const int i1 = i0 + 256;
        float4 v0 = make_float4(0.f, 0.f, 0.f, 0.f);
        float4 v1 = make_float4(0.f, 0.f, 0.f, 0.f);
        if (i0 < NV4) v0 = row[i0];          // both loads in flight (MLP=2)
        if (i1 < NV4) v1 = row[i1];
        int found = -1;
        if (v0.x != 0.f)      found = 4 * i0 + 0;
        else if (v0.y != 0.f) found = 4 * i0 + 1;
        else if (v0.z != 0.f) found = 4 * i0 + 2;
        else if (v0.w != 0.f) found = 4 * i0 + 3;
        else if (v1.x != 0.f) found = 4 * i1 + 0;
        else if (v1.y != 0.f) found = 4 * i1 + 1;
        else if (v1.z != 0.f) found = 4 * i1 + 2;
        else if (v1.w != 0.f) found = 4 * i1 + 3;
        if (found >= 0) {
            s_label = found;
            g_label[b] = found;
            int slot = atomicAdd(&g_cntA[found], 1);
            atomicAdd(&g_cntB[found], 1);
            if (slot < CAP) g_rows[found * CAP + slot] = b;
        }
        __syncthreads();
        if (s_label >= 0) break;
    }

    const int label = s_label;

    // loss vs OLD centers (thread t owns dim t)
    float f = feat[(size_t)b * DIM + t];
    float c = centers[(size_t)label * DIM + t];
    float d = f - c;
    float sq = d * d;
    #pragma unroll
    for (int off = 16; off > 0; off >>= 1)
        sq += __shfl_down_sync(0xFFFFFFFFu, sq, off);
    if ((t & 31) == 0) s_red[t >> 5] = sq;
    __syncthreads();
    if (t < 8) {
        float v = s_red[t];
        #pragma unroll
        for (int off = 4; off > 0; off >>= 1)
            v += __shfl_down_sync(0xFFu, v, off);
        if (t == 0) loss_out[b] = v;
    }
}

// ---------------------------------------------------------------------------
// K2: one thread per float4 of the [C, D] centers matrix (640000 threads).
//   out = k*centers + s * sum(feat rows of class)   k=1-a*n/(n+1), s=a/(n+1)
// Each warp's 32 lanes all belong to ONE class (64 float4/class, half-row
// per warp). The warp reads its own private counter copy (A for cols 0-31,
// B for cols 32-63); the warp's first lane zeroes that copy AFTER the warp's
// load instruction, in program order -> race-free with NO barrier.
// Level-0 loads (count, first two row slots, centers float4) are
// independent; feat gathers are the single dependent level, MLP=2 for the
// dominant n<=2 case.
// ---------------------------------------------------------------------------
__global__ __launch_bounds__(256)
void scale_gather_kernel(const float* __restrict__ centers,
                         const float* __restrict__ feat,
                         float* __restrict__ out_centers) {
    const int i = blockIdx.x * blockDim.x + threadIdx.x;  // float4 index
    const int N4 = NCLS * DIM / 4;                        // 640000
    if (i >= N4) return;
    const int c    = i >> 6;   // class (64 float4 per class row)
    const int col  = i & 63;   // float4 column within class row
    const bool hiW = (col & 32) != 0;  // which half-row warp am I in

    // --- level 0: all independent loads; warp-private counter ---
    const int n = hiW ? g_cntB[c] : g_cntA[c];
    const int2 r01 = *reinterpret_cast<const int2*>(&g_rows[c * CAP]);  // speculative
    float4 a = reinterpret_cast<const float4*>(centers)[i];

    // self-clean: first lane of THIS warp zeroes the copy THIS warp read.
    // In-warp program order (warp-wide LDG issued above precedes this STG).
    if ((col & 31) == 0) {
        if (hiW) g_cntB[c] = 0; else g_cntA[c] = 0;
    }

    const float fn = (float)n;
    const float k = 1.0f - ALPHA * fn / (fn + 1.0f);
    const float s = ALPHA / (fn + 1.0f);
    a.x *= k; a.y *= k; a.z *= k; a.w *= k;

    const float4* feat4 = reinterpret_cast<const float4*>(feat);

    // --- level 1: feat gathers (n<=2 covers 99.4%; both loads co-issued) ---
    if (n >= 1) {
        float4 f0 = feat4[(size_t)r01.x * 64 + col];
        float4 f1 = (n >= 2) ? feat4[(size_t)r01.y * 64 + col]
                             : make_float4(0.f, 0.f, 0.f, 0.f);
        a.x += s * (f0.x + f1.x);
        a.y += s * (f0.y + f1.y);
        a.z += s * (f0.z + f1.z);
        a.w += s * (f0.w + f1.w);
        if (n > 2) {
            const int m = (n <= CAP) ? n : CAP;
            #pragma unroll 1
            for (int j = 2; j < m; ++j) {
                int bj = g_rows[c * CAP + j];
                float4 f = feat4[(size_t)bj * 64 + col];
                a.x += s * f.x; a.y += s * f.y; a.z += s * f.z; a.w += s * f.w;
            }
            if (n > CAP) {
                // exhaustive fallback (statistically unreachable; exact)
                #pragma unroll 1
                for (int bb = 0; bb < BATCH; ++bb) {
                    if (g_label[bb] == c) {
                        bool seen = false;
                        for (int j = 0; j < CAP; ++j)
                            if (g_rows[c * CAP + j] == bb) { seen = true; break; }
                        if (!seen) {
                            float4 f = feat4[(size_t)bb * 64 + col];
                            a.x += s * f.x; a.y += s * f.y;
                            a.z += s * f.z; a.w += s * f.w;
                        }
                    }
                }
            }
        }
    }

    reinterpret_cast<float4*>(out_centers)[i] = a;
}

// ---------------------------------------------------------------------------
extern "C" void kernel_launch(void* const* d_in, const int* in_sizes, int n_in,
                              void* d_out, int out_size) {
    const float* feat    = (const float*)d_in[0];  // [4096, 256]
    const float* onehot  = (const float*)d_in[1];  // [4096, 10000]
    const float* centers = (const float*)d_in[2];  // [10000, 256]

    float* loss_out    = (float*)d_out;            // [4096]
    float* centers_out = (float*)d_out + BATCH;    // [10000, 256]

    scan_loss_kernel<<<BATCH, 256>>>(onehot, feat, centers, loss_out);
    scale_gather_kernel<<<(NCLS * DIM / 4 + 255) / 256, 256>>>(
        centers, feat, centers_out);
}

// round 10
// speedup vs baseline: 1.1911x; 1.1911x over previous
#include <cuda_runtime.h>

#define BATCH 4096
#define NCLS  10000
#define DIM   256
#define ALPHA 0.5f
#define CAP   64   // per-class row-list capacity (overflow handled exactly)

// Scratch (allocation-free: __device__ globals).
// Counters start zeroed (static init); K2 re-zeroes ONLY the touched classes
// (untouched ones are already 0) -> no zero kernel. Dual counters (A/B) give
// each of the two warps covering one class row a private read-then-clean
// sequence in warp program order -> no barriers anywhere in K2.
__device__ int g_cntA[NCLS];        // per-class count, read by warp of cols 0-31
__device__ int g_cntB[NCLS];        // per-class count, read by warp of cols 32-63
__device__ int g_label[BATCH];      // decoded label per row (overflow fallback)
__device__ int g_rows[NCLS * CAP];  // per-class row index list (8B aligned rows)

// ---------------------------------------------------------------------------
// K1: one block per batch row.
//  a) early-exit scan of the onehot row, 8 KB chunks (2 float4/thread, MLP=2)
//  b) finder thread: record label, append row to class list, bump BOTH counts
//  c) all threads: loss ||feat - centers[label]||^2 (gathers hide under the
//     BW-bound scan traffic of other resident blocks)
// ---------------------------------------------------------------------------
__global__ __launch_bounds__(256, 8)
void scan_loss_kernel(const float* __restrict__ onehot,
                      const float* __restrict__ feat,
                      const float* __restrict__ centers,
                      float* __restrict__ loss_out) {
    const int b = blockIdx.x;
    const int t = threadIdx.x;

    __shared__ int s_label;
    __shared__ float s_red[8];
    if (t == 0) s_label = -1;
    __syncthreads();

    const float4* row = reinterpret_cast<const float4*>(onehot + (size_t)b * NCLS);
    const int NV4 = NCLS / 4;  // 2500 float4s

    #pragma unroll 1
    for (int it = 0; it < (NV4 + 511) / 512; ++it) {
        const int i0 = it * 512 + t;
        const int i1 = i0 + 256;
        float4 v0 = make_float4(0.f, 0.f, 0.f, 0.f);
        float4 v1 = make_float4(0.f, 0.f, 0.f, 0.f);
        if (i0 < NV4) v0 = row[i0];          // both loads in flight (MLP=2)
        if (i1 < NV4) v1 = row[i1];
        int found = -1;
        if (v0.x != 0.f)      found = 4 * i0 + 0;
        else if (v0.y != 0.f) found = 4 * i0 + 1;
        else if (v0.z != 0.f) found = 4 * i0 + 2;
        else if (v0.w != 0.f) found = 4 * i0 + 3;
        else if (v1.x != 0.f) found = 4 * i1 + 0;
        else if (v1.y != 0.f) found = 4 * i1 + 1;
        else if (v1.z != 0.f) found = 4 * i1 + 2;
        else if (v1.w != 0.f) found = 4 * i1 + 3;
        if (found >= 0) {
            s_label = found;
            g_label[b] = found;
            int slot = atomicAdd(&g_cntA[found], 1);
            atomicAdd(&g_cntB[found], 1);
            if (slot < CAP) g_rows[found * CAP + slot] = b;
        }
        __syncthreads();
        if (s_label >= 0) break;
    }

    const int label = s_label;

    // loss vs OLD centers (thread t owns dim t)
    float f = feat[(size_t)b * DIM + t];
    float c = centers[(size_t)label * DIM + t];
    float d = f - c;
    float sq = d * d;
    #pragma unroll
    for (int off = 16; off > 0; off >>= 1)
        sq += __shfl_down_sync(0xFFFFFFFFu, sq, off);
    if ((t & 31) == 0) s_red[t >> 5] = sq;
    __syncthreads();
    if (t < 8) {
        float v = s_red[t];
        #pragma unroll
        for (int off = 4; off > 0; off >>= 1)
            v += __shfl_down_sync(0xFFu, v, off);
        if (t == 0) loss_out[b] = v;
    }
}

// ---------------------------------------------------------------------------
// K2: one thread per float4 of the [C, D] centers matrix (640000 threads).
//   out = k*centers + s * sum(feat rows of class)   k=1-a*n/(n+1), s=a/(n+1)
// FAST PATH: n==0 (66% of classes, warp-coherent branch since all 64 threads
// of a class row share n) -> out = centers verbatim; ~8 instructions, no
// division, no row-list load, no counter store (already zero).
// SLOW PATH: n>=1 -> clean the warp's private counter copy (in-warp program
// order after the read), one fast division, feat gathers (MLP=2 for n<=2).
// ---------------------------------------------------------------------------
__global__ __launch_bounds__(256)
void scale_gather_kernel(const float* __restrict__ centers,
                         const float* __restrict__ feat,
                         float* __restrict__ out_centers) {
    const int i = blockIdx.x * blockDim.x + threadIdx.x;  // float4 index; grid exact
    const int c    = i >> 6;           // class (64 float4 per class row)
    const int col  = i & 63;           // float4 column within class row
    const bool hiW = (col & 32) != 0;  // which half-row warp am I in

    // level 0: count + centers float4, independent & co-issued
    const int n = hiW ? g_cntB[c] : g_cntA[c];
    float4 a = reinterpret_cast<const float4*>(centers)[i];

    if (n == 0) {  // 66% of warps: pure copy, counter already zero
        reinterpret_cast<float4*>(out_centers)[i] = a;
        return;
    }

    // self-clean: first lane of THIS warp zeroes the copy THIS warp read
    // (in-warp program order -> race-free, no barrier).
    if ((col & 31) == 0) {
        if (hiW) g_cntB[c] = 0; else g_cntA[c] = 0;
    }

    const float fn = (float)n;
    const float s = __fdividef(ALPHA, fn + 1.0f);
    const float k = 1.0f - fn * s;
    a.x *= k; a.y *= k; a.z *= k; a.w *= k;

    const float4* feat4 = reinterpret_cast<const float4*>(feat);
    const int2 r01 = *reinterpret_cast<const int2*>(&g_rows[c * CAP]);

    // n<=2 covers 99.4% of touched classes; both gathers co-issued (MLP=2)
    float4 f0 = feat4[(size_t)r01.x * 64 + col];
    float4 f1 = (n >= 2) ? feat4[(size_t)r01.y * 64 + col]
                         : make_float4(0.f, 0.f, 0.f, 0.f);
    a.x += s * (f0.x + f1.x);
    a.y += s * (f0.y + f1.y);
    a.z += s * (f0.z + f1.z);
    a.w += s * (f0.w + f1.w);

    if (n > 2) {
        const int m = (n <= CAP) ? n : CAP;
        #pragma unroll 1
        for (int j = 2; j < m; ++j) {
            int bj = g_rows[c * CAP + j];
            float4 f = feat4[(size_t)bj * 64 + col];
            a.x += s * f.x; a.y += s * f.y; a.z += s * f.z; a.w += s * f.w;
        }
        if (n > CAP) {
            // exhaustive fallback (statistically unreachable; exact)
            #pragma unroll 1
            for (int bb = 0; bb < BATCH; ++bb) {
                if (g_label[bb] == c) {
                    bool seen = false;
                    for (int j = 0; j < CAP; ++j)
                        if (g_rows[c * CAP + j] == bb) { seen = true; break; }
                    if (!seen) {
                        float4 f = feat4[(size_t)bb * 64 + col];
                        a.x += s * f.x; a.y += s * f.y;
                        a.z += s * f.z; a.w += s * f.w;
                    }
                }
            }
        }
    }

    reinterpret_cast<float4*>(out_centers)[i] = a;
}

// ---------------------------------------------------------------------------
extern "C" void kernel_launch(void* const* d_in, const int* in_sizes, int n_in,
                              void* d_out, int out_size) {
    const float* feat    = (const float*)d_in[0];  // [4096, 256]
    const float* onehot  = (const float*)d_in[1];  // [4096, 10000]
    const float* centers = (const float*)d_in[2];  // [10000, 256]

    float* loss_out    = (float*)d_out;            // [4096]
    float* centers_out = (float*)d_out + BATCH;    // [10000, 256]

    scan_loss_kernel<<<BATCH, 256>>>(onehot, feat, centers, loss_out);
    scale_gather_kernel<<<NCLS * DIM / 4 / 256, 256>>>(centers, feat, centers_out);
}